// round 3
// baseline (speedup 1.0000x reference)
#include <cuda_runtime.h>

#define NN   50000
#define EE   800000
#define HID  64
#define IND  128
#define OUTD 40

// ---------------- device scratch (no allocations allowed) ----------------
__device__ float g_hlin[NN * HID];      // linear-transformed features (pre-aggregation)
__device__ float g_h0[NN * HID];        // layer outputs (JK cat members)
__device__ float g_h1[NN * HID];
__device__ float g_h2[NN * HID];
__device__ int   g_rowptr[NN + 1];      // CSC row pointers (by dst)
__device__ int   g_cnt[NN];             // histogram / fill cursors
__device__ int   g_srcs[EE];            // src node per edge, grouped by dst
__device__ float g_ews[EE];             // edge weight, grouped by dst
__device__ float g_wpad[192 * 64];      // Wlin padded 40 -> 64 cols
__device__ int   g_is64;                // edge_index dtype flag (1 = int64, 0 = int32)

// selector -> buffer, resolved in device code (no host symbol queries)
__device__ __forceinline__ float* buf_sel(int s) {
    switch (s) {
        case 0:  return g_hlin;
        case 1:  return g_h0;
        case 2:  return g_h1;
        default: return g_h2;
    }
}

__device__ __forceinline__ int clampN(int v) {
    return (v < 0) ? 0 : ((v >= NN) ? NN - 1 : v);
}

// Read edge_index[row][e] under either dtype (little-endian low word for int64).
__device__ __forceinline__ int edge_at(const int* __restrict__ p32, int row, int e, int is64) {
    long long idx = (long long)row * EE + e;
    return is64 ? p32[2 * idx] : p32[idx];
}

// ---------------- dtype detection ----------------
// int64 values < 2^31 -> all high words zero. int32 data -> "high words" are
// random indices in [0, 50000), nonzero with overwhelming probability.
__global__ void detect_kernel(const int* __restrict__ p32) {
    if (threadIdx.x == 0 && blockIdx.x == 0) {
        int any = 0;
        for (int i = 0; i < 64; i++) any |= p32[2 * i + 1];
        g_is64 = (any == 0) ? 1 : 0;
    }
}

// ---------------- CSC build ----------------
__global__ void zero_cnt_kernel() {
    int i = blockIdx.x * blockDim.x + threadIdx.x;
    if (i < NN) g_cnt[i] = 0;
}

__global__ void hist_kernel(const int* __restrict__ ei32) {
    int e = blockIdx.x * blockDim.x + threadIdx.x;
    if (e < EE) {
        int d = clampN(edge_at(ei32, 1, e, g_is64));
        atomicAdd(&g_cnt[d], 1);
    }
}

__global__ void __launch_bounds__(1024) scan_kernel() {
    __shared__ int sums[1024];
    int t = threadIdx.x;
    const int CH = (NN + 1023) / 1024;   // 49
    int beg = t * CH;
    int end = beg + CH;
    if (beg > NN) beg = NN;
    if (end > NN) end = NN;
    int s = 0;
    for (int i = beg; i < end; i++) s += g_cnt[i];
    sums[t] = s;
    __syncthreads();
    // Hillis-Steele inclusive scan
    for (int off = 1; off < 1024; off <<= 1) {
        int v = (t >= off) ? sums[t - off] : 0;
        __syncthreads();
        sums[t] += v;
        __syncthreads();
    }
    int run = (t == 0) ? 0 : sums[t - 1];
    for (int i = beg; i < end; i++) {
        g_rowptr[i] = run;
        run += g_cnt[i];
        g_cnt[i] = 0;   // reset cursors for fill phase
    }
    if (t == 1023) g_rowptr[NN] = sums[1023];
}

__global__ void fill_kernel(const int* __restrict__ ei32,
                            const float* __restrict__ ew) {
    int e = blockIdx.x * blockDim.x + threadIdx.x;
    if (e < EE) {
        int is64 = g_is64;
        int d = clampN(edge_at(ei32, 1, e, is64));
        int s = clampN(edge_at(ei32, 0, e, is64));
        int pos = g_rowptr[d] + atomicAdd(&g_cnt[d], 1);
        g_srcs[pos] = s;
        g_ews[pos]  = ew[e];
    }
}

// ---------------- dense GEMM: Y[N,64] = X[N,K] @ W[K,64] ----------------
// Block: 256 threads = 8 warps. Warp owns 8 rows; lane owns 2 adjacent cols.
// xin != nullptr -> read external input, else read buf_sel(src_sel).
template <int K>
__global__ void __launch_bounds__(256) gemm64_kernel(const float* __restrict__ xin,
                                                     int src_sel, int dst_sel,
                                                     const float* __restrict__ W) {
    __shared__ float ws[K * 64];
    int tid = threadIdx.x;
    for (int i = tid; i < K * 64; i += 256) ws[i] = W[i];
    __syncthreads();

    const float* X = xin ? xin : buf_sel(src_sel);
    float*       Y = buf_sel(dst_sel);

    int w = tid >> 5, lane = tid & 31;
    int row0 = blockIdx.x * 64 + w * 8;

    const float* xp[8];
#pragma unroll
    for (int i = 0; i < 8; i++) {
        int r = row0 + i;
        if (r >= NN) r = NN - 1;   // clamp (dup compute, store guarded)
        xp[i] = X + (size_t)r * K;
    }

    float acc0[8], acc1[8];
#pragma unroll
    for (int i = 0; i < 8; i++) { acc0[i] = 0.f; acc1[i] = 0.f; }

#pragma unroll 4
    for (int k = 0; k < K; k += 4) {
        float2 wv0 = *(const float2*)&ws[(k + 0) * 64 + lane * 2];
        float2 wv1 = *(const float2*)&ws[(k + 1) * 64 + lane * 2];
        float2 wv2 = *(const float2*)&ws[(k + 2) * 64 + lane * 2];
        float2 wv3 = *(const float2*)&ws[(k + 3) * 64 + lane * 2];
#pragma unroll
        for (int i = 0; i < 8; i++) {
            float4 xv = *(const float4*)(xp[i] + k);
            acc0[i] = fmaf(xv.x, wv0.x, acc0[i]); acc1[i] = fmaf(xv.x, wv0.y, acc1[i]);
            acc0[i] = fmaf(xv.y, wv1.x, acc0[i]); acc1[i] = fmaf(xv.y, wv1.y, acc1[i]);
            acc0[i] = fmaf(xv.z, wv2.x, acc0[i]); acc1[i] = fmaf(xv.z, wv2.y, acc1[i]);
            acc0[i] = fmaf(xv.w, wv3.x, acc0[i]); acc1[i] = fmaf(xv.w, wv3.y, acc1[i]);
        }
    }

#pragma unroll
    for (int i = 0; i < 8; i++) {
        int r = row0 + i;
        if (r < NN) {
            float2 o; o.x = acc0[i]; o.y = acc1[i];
            *(float2*)&Y[(size_t)r * 64 + lane * 2] = o;
        }
    }
}

// ---------------- aggregation: warp per node, no atomics ----------------
// hout[n] = relu( sum_{e: dst=n} w_e * hlin[src_e] + bias )
__global__ void __launch_bounds__(256) agg_kernel(int dst_sel,
                                                  const float* __restrict__ bias) {
    int gw   = (blockIdx.x * 256 + threadIdx.x) >> 5;
    int lane = threadIdx.x & 31;
    if (gw >= NN) return;

    const float* hlin = g_hlin;
    float*       hout = buf_sel(dst_sel);

    int beg = g_rowptr[gw], end = g_rowptr[gw + 1];
    float a0 = 0.f, a1 = 0.f;

    int e = beg;
    if (e < end) {
        int   s  = g_srcs[e];
        float wt = g_ews[e];
        while (true) {
            int en = e + 1;
            int sn = 0; float wn = 0.f;
            if (en < end) { sn = g_srcs[en]; wn = g_ews[en]; }  // prefetch next edge
            float2 hv = *(const float2*)&hlin[(size_t)s * 64 + lane * 2];
            a0 = fmaf(wt, hv.x, a0);
            a1 = fmaf(wt, hv.y, a1);
            if (en >= end) break;
            e = en; s = sn; wt = wn;
        }
    }

    float b0 = bias[lane * 2], b1 = bias[lane * 2 + 1];
    float2 o;
    o.x = fmaxf(a0 + b0, 0.f);
    o.y = fmaxf(a1 + b1, 0.f);
    *(float2*)&hout[(size_t)gw * 64 + lane * 2] = o;
}

// ---------------- pad Wlin [192,40] -> g_wpad [192,64] ----------------
__global__ void pad_wlin_kernel(const float* __restrict__ Wlin) {
    int i = blockIdx.x * blockDim.x + threadIdx.x;
    if (i < 192 * 64) {
        int k = i >> 6, c = i & 63;
        g_wpad[i] = (c < OUTD) ? Wlin[k * OUTD + c] : 0.f;
    }
}

// ---------------- final: out = [h0|h1|h2] @ Wlin + blin ----------------
__global__ void __launch_bounds__(256) final_kernel(const float* __restrict__ blin,
                                                    float* __restrict__ out) {
    int tid = threadIdx.x;
    int w = tid >> 5, lane = tid & 31;
    int row0 = blockIdx.x * 64 + w * 8;

    int rr[8];
#pragma unroll
    for (int i = 0; i < 8; i++) {
        int r = row0 + i;
        rr[i] = (r < NN) ? r : NN - 1;
    }

    float acc0[8], acc1[8];
#pragma unroll
    for (int i = 0; i < 8; i++) { acc0[i] = 0.f; acc1[i] = 0.f; }

#pragma unroll 1
    for (int l = 0; l < 3; l++) {
        const float* Hp = (l == 0) ? g_h0 : (l == 1) ? g_h1 : g_h2;
        const float* wp = g_wpad + l * 64 * 64;
#pragma unroll 4
        for (int k = 0; k < 64; k += 4) {
            float2 wv0 = *(const float2*)&wp[(k + 0) * 64 + lane * 2];
            float2 wv1 = *(const float2*)&wp[(k + 1) * 64 + lane * 2];
            float2 wv2 = *(const float2*)&wp[(k + 2) * 64 + lane * 2];
            float2 wv3 = *(const float2*)&wp[(k + 3) * 64 + lane * 2];
#pragma unroll
            for (int i = 0; i < 8; i++) {
                float4 xv = *(const float4*)&Hp[(size_t)rr[i] * 64 + k];
                acc0[i] = fmaf(xv.x, wv0.x, acc0[i]); acc1[i] = fmaf(xv.x, wv0.y, acc1[i]);
                acc0[i] = fmaf(xv.y, wv1.x, acc0[i]); acc1[i] = fmaf(xv.y, wv1.y, acc1[i]);
                acc0[i] = fmaf(xv.z, wv2.x, acc0[i]); acc1[i] = fmaf(xv.z, wv2.y, acc1[i]);
                acc0[i] = fmaf(xv.w, wv3.x, acc0[i]); acc1[i] = fmaf(xv.w, wv3.y, acc1[i]);
            }
        }
    }

    int c = lane * 2;
    if (c < OUTD) {     // c even <= 38 -> c+1 = 39 also valid
        float b0 = blin[c], b1 = blin[c + 1];
#pragma unroll
        for (int i = 0; i < 8; i++) {
            int r = row0 + i;
            if (r < NN) {
                float2 o; o.x = acc0[i] + b0; o.y = acc1[i] + b1;
                *(float2*)&out[(size_t)r * OUTD + c] = o;
            }
        }
    }
}

// ---------------- launch ----------------
extern "C" void kernel_launch(void* const* d_in, const int* in_sizes, int n_in,
                              void* d_out, int out_size) {
    const float* x    = (const float*)d_in[0];
    const int*   ei32 = (const int*)d_in[1];     // int32 view; dtype detected on device
    const float* ew   = (const float*)d_in[2];
    const float* W1 = (const float*)d_in[3];
    const float* b1 = (const float*)d_in[4];
    const float* W2 = (const float*)d_in[5];
    const float* b2 = (const float*)d_in[6];
    const float* W3 = (const float*)d_in[7];
    const float* b3 = (const float*)d_in[8];
    const float* Wl = (const float*)d_in[9];
    const float* bl = (const float*)d_in[10];
    float* out = (float*)d_out;

    // CSC build (once per launch; captured into the graph)
    detect_kernel<<<1, 32>>>(ei32);
    zero_cnt_kernel<<<(NN + 255) / 256, 256>>>();
    hist_kernel<<<(EE + 255) / 256, 256>>>(ei32);
    scan_kernel<<<1, 1024>>>();
    fill_kernel<<<(EE + 255) / 256, 256>>>(ei32, ew);
    pad_wlin_kernel<<<(192 * 64 + 255) / 256, 256>>>(Wl);

    const int GB = (NN + 63) / 64;            // 782
    const int AB = (NN * 32 + 255) / 256;     // 6250

    // layer 1: x -> g_hlin -> agg -> g_h0
    gemm64_kernel<IND><<<GB, 256>>>(x, -1, 0, W1);
    agg_kernel<<<AB, 256>>>(1, b1);

    // layer 2: g_h0 -> g_hlin -> agg -> g_h1
    gemm64_kernel<HID><<<GB, 256>>>(nullptr, 1, 0, W2);
    agg_kernel<<<AB, 256>>>(2, b2);

    // layer 3: g_h1 -> g_hlin -> agg -> g_h2
    gemm64_kernel<HID><<<GB, 256>>>(nullptr, 2, 0, W3);
    agg_kernel<<<AB, 256>>>(3, b3);

    final_kernel<<<GB, 256>>>(bl, out);
}

// round 4
// speedup vs baseline: 1.2665x; 1.2665x over previous
#include <cuda_runtime.h>

#define NN   50000
#define EE   800000
#define HID  64
#define IND  128
#define OUTD 40
#define NBLK ((NN + 255) / 256)   // 196 scan blocks

// ---------------- device scratch (no allocations allowed) ----------------
__device__ float g_hlin[NN * HID];      // linear-transformed features (pre-aggregation)
__device__ float g_h0[NN * HID];        // layer outputs (JK cat members)
__device__ float g_h1[NN * HID];
__device__ float g_h2[NN * HID];
__device__ int   g_rowptr[NN + 1];      // CSC row pointers (by dst)
__device__ int   g_cnt[NN];             // histogram / fill cursors
__device__ int   g_bsum[NBLK];          // per-block sums -> exclusive offsets
__device__ int   g_srcs[EE];            // src node per edge, grouped by dst
__device__ float g_ews[EE];             // edge weight, grouped by dst
__device__ float g_wpad[192 * 64];      // Wlin padded 40 -> 64 cols
__device__ int   g_is64;                // edge_index dtype flag (1 = int64, 0 = int32)

// selector -> buffer, resolved in device code (no host symbol queries)
__device__ __forceinline__ float* buf_sel(int s) {
    switch (s) {
        case 0:  return g_hlin;
        case 1:  return g_h0;
        case 2:  return g_h1;
        default: return g_h2;
    }
}

__device__ __forceinline__ int clampN(int v) {
    return (v < 0) ? 0 : ((v >= NN) ? NN - 1 : v);
}

// Read edge_index[row][e] under either dtype (little-endian low word for int64).
__device__ __forceinline__ int edge_at(const int* __restrict__ p32, int row, int e, int is64) {
    long long idx = (long long)row * EE + e;
    return is64 ? p32[2 * idx] : p32[idx];
}

// ---------------- dtype detection ----------------
__global__ void detect_kernel(const int* __restrict__ p32) {
    if (threadIdx.x == 0 && blockIdx.x == 0) {
        int any = 0;
        for (int i = 0; i < 64; i++) any |= p32[2 * i + 1];
        g_is64 = (any == 0) ? 1 : 0;
    }
}

// ---------------- CSC build ----------------
__global__ void zero_cnt_kernel() {
    int i = blockIdx.x * blockDim.x + threadIdx.x;
    if (i < NN) g_cnt[i] = 0;
}

__global__ void hist_kernel(const int* __restrict__ ei32) {
    int e = blockIdx.x * blockDim.x + threadIdx.x;
    if (e < EE) {
        int d = clampN(edge_at(ei32, 1, e, g_is64));
        atomicAdd(&g_cnt[d], 1);
    }
}

// block-wide exclusive scan over 256 threads (shuffle + smem)
__device__ __forceinline__ int block_excl_scan_256(int v, int tid) {
    int lane = tid & 31, w = tid >> 5;
    int x = v;
#pragma unroll
    for (int o = 1; o < 32; o <<= 1) {
        int y = __shfl_up_sync(0xFFFFFFFFu, x, o);
        if (lane >= o) x += y;
    }
    __shared__ int wsum[8];
    if (lane == 31) wsum[w] = x;
    __syncthreads();
    if (w == 0) {
        int s = (lane < 8) ? wsum[lane] : 0;
#pragma unroll
        for (int o = 1; o < 8; o <<= 1) {
            int y = __shfl_up_sync(0xFFFFFFFFu, s, o);
            if (lane >= o) s += y;
        }
        if (lane < 8) wsum[lane] = s;
    }
    __syncthreads();
    int incl = x + ((w > 0) ? wsum[w - 1] : 0);
    return incl - v;
}

// phase 1: per-block chunk sums
__global__ void __launch_bounds__(256) scan_p1_kernel() {
    int i = blockIdx.x * 256 + threadIdx.x;
    int v = (i < NN) ? g_cnt[i] : 0;
#pragma unroll
    for (int o = 16; o > 0; o >>= 1) v += __shfl_down_sync(0xFFFFFFFFu, v, o);
    __shared__ int wsum[8];
    if ((threadIdx.x & 31) == 0) wsum[threadIdx.x >> 5] = v;
    __syncthreads();
    if (threadIdx.x == 0) {
        int s = 0;
#pragma unroll
        for (int w = 0; w < 8; w++) s += wsum[w];
        g_bsum[blockIdx.x] = s;
    }
}

// phase 2: exclusive scan of 196 block sums (single block)
__global__ void __launch_bounds__(256) scan_p2_kernel() {
    int t = threadIdx.x;
    int v = (t < NBLK) ? g_bsum[t] : 0;
    int excl = block_excl_scan_256(v, t);
    if (t < NBLK) g_bsum[t] = excl;
    if (t == NBLK - 1) g_rowptr[NN] = excl + v;   // total edge count
}

// phase 3: block-local exclusive scan + offset; write rowptr, reset cursors
__global__ void __launch_bounds__(256) scan_p3_kernel() {
    int i = blockIdx.x * 256 + threadIdx.x;
    int v = (i < NN) ? g_cnt[i] : 0;
    int excl = block_excl_scan_256(v, threadIdx.x);
    if (i < NN) {
        g_rowptr[i] = g_bsum[blockIdx.x] + excl;
        g_cnt[i] = 0;
    }
}

__global__ void fill_kernel(const int* __restrict__ ei32,
                            const float* __restrict__ ew) {
    int e = blockIdx.x * blockDim.x + threadIdx.x;
    if (e < EE) {
        int is64 = g_is64;
        int d = clampN(edge_at(ei32, 1, e, is64));
        int s = clampN(edge_at(ei32, 0, e, is64));
        int pos = g_rowptr[d] + atomicAdd(&g_cnt[d], 1);
        g_srcs[pos] = s;
        g_ews[pos]  = ew[e];
    }
}

// ---------------- dense GEMM: Y[N,64] = X[N,K] @ W[K,64] ----------------
template <int K>
__global__ void __launch_bounds__(256) gemm64_kernel(const float* __restrict__ xin,
                                                     int src_sel, int dst_sel,
                                                     const float* __restrict__ W) {
    __shared__ float ws[K * 64];
    int tid = threadIdx.x;
    for (int i = tid; i < K * 64; i += 256) ws[i] = W[i];
    __syncthreads();

    const float* X = xin ? xin : buf_sel(src_sel);
    float*       Y = buf_sel(dst_sel);

    int w = tid >> 5, lane = tid & 31;
    int row0 = blockIdx.x * 64 + w * 8;

    const float* xp[8];
#pragma unroll
    for (int i = 0; i < 8; i++) {
        int r = row0 + i;
        if (r >= NN) r = NN - 1;   // clamp (dup compute, store guarded)
        xp[i] = X + (size_t)r * K;
    }

    float acc0[8], acc1[8];
#pragma unroll
    for (int i = 0; i < 8; i++) { acc0[i] = 0.f; acc1[i] = 0.f; }

#pragma unroll 4
    for (int k = 0; k < K; k += 4) {
        float2 wv0 = *(const float2*)&ws[(k + 0) * 64 + lane * 2];
        float2 wv1 = *(const float2*)&ws[(k + 1) * 64 + lane * 2];
        float2 wv2 = *(const float2*)&ws[(k + 2) * 64 + lane * 2];
        float2 wv3 = *(const float2*)&ws[(k + 3) * 64 + lane * 2];
#pragma unroll
        for (int i = 0; i < 8; i++) {
            float4 xv = *(const float4*)(xp[i] + k);
            acc0[i] = fmaf(xv.x, wv0.x, acc0[i]); acc1[i] = fmaf(xv.x, wv0.y, acc1[i]);
            acc0[i] = fmaf(xv.y, wv1.x, acc0[i]); acc1[i] = fmaf(xv.y, wv1.y, acc1[i]);
            acc0[i] = fmaf(xv.z, wv2.x, acc0[i]); acc1[i] = fmaf(xv.z, wv2.y, acc1[i]);
            acc0[i] = fmaf(xv.w, wv3.x, acc0[i]); acc1[i] = fmaf(xv.w, wv3.y, acc1[i]);
        }
    }

#pragma unroll
    for (int i = 0; i < 8; i++) {
        int r = row0 + i;
        if (r < NN) {
            float2 o; o.x = acc0[i]; o.y = acc1[i];
            *(float2*)&Y[(size_t)r * 64 + lane * 2] = o;
        }
    }
}

// ---------------- aggregation: warp per node, no atomics ----------------
__global__ void __launch_bounds__(256) agg_kernel(int dst_sel,
                                                  const float* __restrict__ bias) {
    int gw   = (blockIdx.x * 256 + threadIdx.x) >> 5;
    int lane = threadIdx.x & 31;
    if (gw >= NN) return;

    const float* hlin = g_hlin;
    float*       hout = buf_sel(dst_sel);

    int beg = g_rowptr[gw], end = g_rowptr[gw + 1];
    float a0 = 0.f, a1 = 0.f;

    int e = beg;
    if (e < end) {
        int   s  = g_srcs[e];
        float wt = g_ews[e];
        while (true) {
            int en = e + 1;
            int sn = 0; float wn = 0.f;
            if (en < end) { sn = g_srcs[en]; wn = g_ews[en]; }  // prefetch next edge
            float2 hv = *(const float2*)&hlin[(size_t)s * 64 + lane * 2];
            a0 = fmaf(wt, hv.x, a0);
            a1 = fmaf(wt, hv.y, a1);
            if (en >= end) break;
            e = en; s = sn; wt = wn;
        }
    }

    float b0 = bias[lane * 2], b1 = bias[lane * 2 + 1];
    float2 o;
    o.x = fmaxf(a0 + b0, 0.f);
    o.y = fmaxf(a1 + b1, 0.f);
    *(float2*)&hout[(size_t)gw * 64 + lane * 2] = o;
}

// ---------------- pad Wlin [192,40] -> g_wpad [192,64] ----------------
__global__ void pad_wlin_kernel(const float* __restrict__ Wlin) {
    int i = blockIdx.x * blockDim.x + threadIdx.x;
    if (i < 192 * 64) {
        int k = i >> 6, c = i & 63;
        g_wpad[i] = (c < OUTD) ? Wlin[k * OUTD + c] : 0.f;
    }
}

// ---------------- final: out = [h0|h1|h2] @ Wlin + blin ----------------
__global__ void __launch_bounds__(256) final_kernel(const float* __restrict__ blin,
                                                    float* __restrict__ out) {
    int tid = threadIdx.x;
    int w = tid >> 5, lane = tid & 31;
    int row0 = blockIdx.x * 64 + w * 8;

    int rr[8];
#pragma unroll
    for (int i = 0; i < 8; i++) {
        int r = row0 + i;
        rr[i] = (r < NN) ? r : NN - 1;
    }

    float acc0[8], acc1[8];
#pragma unroll
    for (int i = 0; i < 8; i++) { acc0[i] = 0.f; acc1[i] = 0.f; }

#pragma unroll 1
    for (int l = 0; l < 3; l++) {
        const float* Hp = (l == 0) ? g_h0 : (l == 1) ? g_h1 : g_h2;
        const float* wp = g_wpad + l * 64 * 64;
#pragma unroll 4
        for (int k = 0; k < 64; k += 4) {
            float2 wv0 = *(const float2*)&wp[(k + 0) * 64 + lane * 2];
            float2 wv1 = *(const float2*)&wp[(k + 1) * 64 + lane * 2];
            float2 wv2 = *(const float2*)&wp[(k + 2) * 64 + lane * 2];
            float2 wv3 = *(const float2*)&wp[(k + 3) * 64 + lane * 2];
#pragma unroll
            for (int i = 0; i < 8; i++) {
                float4 xv = *(const float4*)&Hp[(size_t)rr[i] * 64 + k];
                acc0[i] = fmaf(xv.x, wv0.x, acc0[i]); acc1[i] = fmaf(xv.x, wv0.y, acc1[i]);
                acc0[i] = fmaf(xv.y, wv1.x, acc0[i]); acc1[i] = fmaf(xv.y, wv1.y, acc1[i]);
                acc0[i] = fmaf(xv.z, wv2.x, acc0[i]); acc1[i] = fmaf(xv.z, wv2.y, acc1[i]);
                acc0[i] = fmaf(xv.w, wv3.x, acc0[i]); acc1[i] = fmaf(xv.w, wv3.y, acc1[i]);
            }
        }
    }

    int c = lane * 2;
    if (c < OUTD) {     // c even <= 38 -> c+1 = 39 also valid
        float b0 = blin[c], b1 = blin[c + 1];
#pragma unroll
        for (int i = 0; i < 8; i++) {
            int r = row0 + i;
            if (r < NN) {
                float2 o; o.x = acc0[i] + b0; o.y = acc1[i] + b1;
                *(float2*)&out[(size_t)r * OUTD + c] = o;
            }
        }
    }
}

// ---------------- launch ----------------
extern "C" void kernel_launch(void* const* d_in, const int* in_sizes, int n_in,
                              void* d_out, int out_size) {
    const float* x    = (const float*)d_in[0];
    const int*   ei32 = (const int*)d_in[1];     // int32 view; dtype detected on device
    const float* ew   = (const float*)d_in[2];
    const float* W1 = (const float*)d_in[3];
    const float* b1 = (const float*)d_in[4];
    const float* W2 = (const float*)d_in[5];
    const float* b2 = (const float*)d_in[6];
    const float* W3 = (const float*)d_in[7];
    const float* b3 = (const float*)d_in[8];
    const float* Wl = (const float*)d_in[9];
    const float* bl = (const float*)d_in[10];
    float* out = (float*)d_out;

    // CSC build (once per launch; captured into the graph)
    detect_kernel<<<1, 32>>>(ei32);
    zero_cnt_kernel<<<NBLK, 256>>>();
    hist_kernel<<<(EE + 255) / 256, 256>>>(ei32);
    scan_p1_kernel<<<NBLK, 256>>>();
    scan_p2_kernel<<<1, 256>>>();
    scan_p3_kernel<<<NBLK, 256>>>();
    fill_kernel<<<(EE + 255) / 256, 256>>>(ei32, ew);
    pad_wlin_kernel<<<(192 * 64 + 255) / 256, 256>>>(Wl);

    const int GB = (NN + 63) / 64;            // 782
    const int AB = (NN * 32 + 255) / 256;     // 6250

    // layer 1: x -> g_hlin -> agg -> g_h0
    gemm64_kernel<IND><<<GB, 256>>>(x, -1, 0, W1);
    agg_kernel<<<AB, 256>>>(1, b1);

    // layer 2: g_h0 -> g_hlin -> agg -> g_h1
    gemm64_kernel<HID><<<GB, 256>>>(nullptr, 1, 0, W2);
    agg_kernel<<<AB, 256>>>(2, b2);

    // layer 3: g_h1 -> g_hlin -> agg -> g_h2
    gemm64_kernel<HID><<<GB, 256>>>(nullptr, 2, 0, W3);
    agg_kernel<<<AB, 256>>>(3, b3);

    final_kernel<<<GB, 256>>>(bl, out);
}